// round 10
// baseline (speedup 1.0000x reference)
#include <cuda_runtime.h>
#include <cuda_bf16.h>
#include <math.h>

#define H_DIM 2
#define L_LAYERS 4
#define R_RELS 16
#define B_BASES 8
#define N_NODES 1000000
#define E_EDGES 16000000

// ---- device scratch (allocation-free rule) --------------------------------
__device__ float2 g_x[N_NODES];      // only used for the post-skip input (layer 2)
__device__ float2 g_hA[N_NODES];
__device__ float2 g_hB[N_NODES];
__device__ float2 g_skip[N_NODES];
__device__ float4 g_W[L_LAYERS * R_RELS];   // (w00,w01,w10,w11) per [l][r]
__device__ float  g_acc;

// ---------------------------------------------------------------------------
__global__ void compute_weights_kernel(const float* __restrict__ V,
                                       const float* __restrict__ comp) {
    int tid = threadIdx.x;
    if (tid >= L_LAYERS * R_RELS) return;
    int l = tid / R_RELS, r = tid % R_RELS;
    float w0 = 0.f, w1 = 0.f, w2 = 0.f, w3 = 0.f;
    #pragma unroll
    for (int b = 0; b < B_BASES; b++) {
        float c = comp[(l * R_RELS + r) * B_BASES + b];
        const float* v = V + ((l * B_BASES + b) * 4);
        w0 += c * v[0]; w1 += c * v[1]; w2 += c * v[2]; w3 += c * v[3];
    }
    g_W[tid] = make_float4(w0, w1, w2, w3);
}

// hA = hB = 0; acc = 0  (float4 writes, 2 nodes/thread)
__global__ void zero_kernel() {
    int i = blockIdx.x * blockDim.x + threadIdx.x;
    if (i == 0) g_acc = 0.f;
    if (i >= N_NODES / 2) return;
    ((float4*)g_hA)[i] = make_float4(0.f, 0.f, 0.f, 0.f);
    ((float4*)g_hB)[i] = make_float4(0.f, 0.f, 0.f, 0.f);
}

// ---------------------------------------------------------------------------
// Edge kernel (proven shape): 4 edges/thread, __ldcs streams, float2 RED.
// MODE 0: gather xin[src] raw.
// MODE 1: gather xin[src] then apply relu(v + bias_in) inline (fused epilogue
//         of the previous layer — saves a full node pass).
template <int MODE>
__global__ void __launch_bounds__(256) edge_kernel(
        const float2* __restrict__ xin,
        float2* __restrict__ hout,
        const int4* __restrict__ src4,
        const int4* __restrict__ dst4,
        const int4* __restrict__ type4,
        const float4* __restrict__ norm4,
        int l, float bx, float by) {
    __shared__ float4 sW[R_RELS];
    if (threadIdx.x < R_RELS) sW[threadIdx.x] = g_W[l * R_RELS + threadIdx.x];
    __syncthreads();

    int i = blockIdx.x * blockDim.x + threadIdx.x;
    if (i >= E_EDGES / 4) return;

    int4   s  = __ldcs(&src4[i]);
    int4   d  = __ldcs(&dst4[i]);
    int4   t  = __ldcs(&type4[i]);
    float4 nm = __ldcs(&norm4[i]);

    int   ss[4] = {s.x, s.y, s.z, s.w};
    int   dd[4] = {d.x, d.y, d.z, d.w};
    int   tt[4] = {t.x, t.y, t.z, t.w};
    float nn[4] = {nm.x, nm.y, nm.z, nm.w};

    #pragma unroll
    for (int k = 0; k < 4; k++) {
        float2 xs = __ldg(&xin[ss[k]]);
        if (MODE == 1) {
            xs.x = fmaxf(xs.x + bx, 0.f);
            xs.y = fmaxf(xs.y + by, 0.f);
        }
        float4 w = sW[tt[k]];
        float mx = (xs.x * w.x + xs.y * w.z) * nn[k];
        float my = (xs.x * w.y + xs.y * w.w) * nn[k];
        atomicAdd(&hout[dd[k]], make_float2(mx, my));
    }
}

// ---------------------------------------------------------------------------
// After layer 1: x = relu(hB + b1) + feat; skip = x; re-zero hA and hB.
__global__ void epi_skip_kernel(const float* __restrict__ bias,
                                const float2* __restrict__ feat) {
    int i = blockIdx.x * blockDim.x + threadIdx.x;
    if (i >= N_NODES) return;
    float2 h = g_hB[i];
    float2 f = feat[i];
    float2 v = make_float2(fmaxf(h.x + __ldg(&bias[2]), 0.f) + f.x,
                           fmaxf(h.y + __ldg(&bias[3]), 0.f) + f.y);
    g_x[i] = v;
    g_skip[i] = v;
    g_hA[i] = make_float2(0.f, 0.f);
    g_hB[i] = make_float2(0.f, 0.f);
}

// ---------------------------------------------------------------------------
// Fused final epilogue + dot:  acc += w . ((hB + b3) + skip)
__global__ void dot_kernel(const float4* __restrict__ w4,
                           const float* __restrict__ bias) {
    float b3x = __ldg(&bias[6]);
    float b3y = __ldg(&bias[7]);
    const int npairs = N_NODES / 2;
    float sum = 0.f;
    for (int i = blockIdx.x * blockDim.x + threadIdx.x; i < npairs;
         i += gridDim.x * blockDim.x) {
        float4 w = __ldcs(&w4[i]);
        float2 ha = g_hB[2 * i],   hb = g_hB[2 * i + 1];
        float2 sa = g_skip[2 * i], sb = g_skip[2 * i + 1];
        sum += w.x * (ha.x + b3x + sa.x) + w.y * (ha.y + b3y + sa.y)
             + w.z * (hb.x + b3x + sb.x) + w.w * (hb.y + b3y + sb.y);
    }
    #pragma unroll
    for (int off = 16; off > 0; off >>= 1)
        sum += __shfl_down_sync(0xFFFFFFFFu, sum, off);
    __shared__ float ws[8];
    int lane = threadIdx.x & 31, wid = threadIdx.x >> 5;
    if (lane == 0) ws[wid] = sum;
    __syncthreads();
    if (wid == 0) {
        sum = (lane < (blockDim.x >> 5)) ? ws[lane] : 0.f;
        #pragma unroll
        for (int off = 4; off > 0; off >>= 1)
            sum += __shfl_down_sync(0xFFFFFFFFu, sum, off);
        if (lane == 0) atomicAdd(&g_acc, sum);
    }
}

__global__ void finalize_kernel(const float* __restrict__ b_mlp,
                                float* __restrict__ out) {
    float logit = g_acc + b_mlp[0];
    out[0] = 1.f / (1.f + expf(-logit));
}

// ---------------------------------------------------------------------------
extern "C" void kernel_launch(void* const* d_in, const int* in_sizes, int n_in,
                              void* d_out, int out_size) {
    const float* features  = (const float*)d_in[0];
    const float* norm      = (const float*)d_in[1];
    const float* V         = (const float*)d_in[2];
    const float* comp      = (const float*)d_in[3];
    const float* bias      = (const float*)d_in[4];
    const float* w_mlp     = (const float*)d_in[5];
    const float* b_mlp     = (const float*)d_in[6];
    const int*   edge_src  = (const int*)d_in[7];
    const int*   edge_dst  = (const int*)d_in[8];
    const int*   edge_type = (const int*)d_in[9];
    float*       out       = (float*)d_out;

    const int TB = 256;
    const int node_blocks = (N_NODES + TB - 1) / TB;
    const int edge_blocks = (E_EDGES / 4 + TB - 1) / TB;   // 15625

    const int4*   s4 = (const int4*)edge_src;
    const int4*   d4 = (const int4*)edge_dst;
    const int4*   t4 = (const int4*)edge_type;
    const float4* n4 = (const float4*)norm;

    void *pA = nullptr, *pB = nullptr, *pX = nullptr;
    cudaGetSymbolAddress(&pA, g_hA);
    cudaGetSymbolAddress(&pB, g_hB);
    cudaGetSymbolAddress(&pX, g_x);
    float2* hA = (float2*)pA;
    float2* hB = (float2*)pB;
    const float2* fx = (const float2*)pX;

    // bias is tiny and device-resident; fetch once per launch is not allowed
    // (no sync copies). Pass b0/b2 via kernel by reading bias on device:
    // use MODE 1 kernels that take bias values read from constant inputs.
    // Since we cannot read device memory on host, pass the bias POINTER value
    // indices instead: use small helper reads inside the kernels via __ldg on
    // a pointer. To keep the template signature, we pass bias as two floats
    // loaded in a tiny setup kernel into g_W's tail? Simpler: pass the pointer.

    compute_weights_kernel<<<1, 64>>>(V, comp);
    zero_kernel<<<(N_NODES / 2 + TB - 1) / TB, TB>>>();

    // layer 0: gather feat -> hA
    edge_kernel<0><<<edge_blocks, TB>>>((const float2*)features, hA,
                                        s4, d4, t4, n4, 0, 0.f, 0.f);
    // layer 1: gather relu(hA + b0) inline -> hB   (b0 read via bias ptr)
    // bias values must come from device memory; MODE 2 variant reads them.
    // Implemented below with a pointer-taking kernel.
    {
        // MODE 1 with bias pointer: reuse template by passing values via
        // a tiny wrapper kernel is not possible; instead we use the
        // pointer-based variant defined right after this comment.
    }
    // fallthrough handled by dedicated launches below
    // layer 1:
    extern __global__ void edge_relu_kernel(const float2*, float2*,
                                            const int4*, const int4*,
                                            const int4*, const float4*,
                                            int, const float*, int);
    edge_relu_kernel<<<edge_blocks, TB>>>(hA, hB, s4, d4, t4, n4,
                                          1, bias, 0);
    // epilogue of layer 1 (skip) + re-zero both h buffers
    epi_skip_kernel<<<node_blocks, TB>>>(bias, (const float2*)features);

    // layer 2: gather x -> hA
    edge_kernel<0><<<edge_blocks, TB>>>(fx, hA, s4, d4, t4, n4, 2, 0.f, 0.f);
    // layer 3: gather relu(hA + b2) inline -> hB
    edge_relu_kernel<<<edge_blocks, TB>>>(hA, hB, s4, d4, t4, n4,
                                          3, bias, 2);

    dot_kernel<<<1024, TB>>>((const float4*)w_mlp, bias);
    finalize_kernel<<<1, 1>>>(b_mlp, out);
}

// ---------------------------------------------------------------------------
// MODE-1 edge kernel reading bias from device memory (bias of layer `bl`).
__global__ void __launch_bounds__(256) edge_relu_kernel(
        const float2* __restrict__ hin,
        float2* __restrict__ hout,
        const int4* __restrict__ src4,
        const int4* __restrict__ dst4,
        const int4* __restrict__ type4,
        const float4* __restrict__ norm4,
        int l, const float* __restrict__ bias, int bl) {
    __shared__ float4 sW[R_RELS];
    __shared__ float sB[2];
    if (threadIdx.x < R_RELS) sW[threadIdx.x] = g_W[l * R_RELS + threadIdx.x];
    if (threadIdx.x == 0) {
        sB[0] = __ldg(&bias[2 * bl]);
        sB[1] = __ldg(&bias[2 * bl + 1]);
    }
    __syncthreads();
    float bx = sB[0], by = sB[1];

    int i = blockIdx.x * blockDim.x + threadIdx.x;
    if (i >= E_EDGES / 4) return;

    int4   s  = __ldcs(&src4[i]);
    int4   d  = __ldcs(&dst4[i]);
    int4   t  = __ldcs(&type4[i]);
    float4 nm = __ldcs(&norm4[i]);

    int   ss[4] = {s.x, s.y, s.z, s.w};
    int   dd[4] = {d.x, d.y, d.z, d.w};
    int   tt[4] = {t.x, t.y, t.z, t.w};
    float nn[4] = {nm.x, nm.y, nm.z, nm.w};

    #pragma unroll
    for (int k = 0; k < 4; k++) {
        float2 xs = __ldg(&hin[ss[k]]);
        xs.x = fmaxf(xs.x + bx, 0.f);
        xs.y = fmaxf(xs.y + by, 0.f);
        float4 w = sW[tt[k]];
        float mx = (xs.x * w.x + xs.y * w.z) * nn[k];
        float my = (xs.x * w.y + xs.y * w.w) * nn[k];
        atomicAdd(&hout[dd[k]], make_float2(mx, my));
    }
}

// round 11
// speedup vs baseline: 1.0039x; 1.0039x over previous
#include <cuda_runtime.h>
#include <cuda_bf16.h>
#include <math.h>

#define H_DIM 2
#define L_LAYERS 4
#define R_RELS 16
#define B_BASES 8
#define N_NODES 1000000
#define E_EDGES 16000000

// ---- device scratch (allocation-free rule) --------------------------------
__device__ float2 g_x[N_NODES];
__device__ float2 g_h[N_NODES];
__device__ float2 g_skip[N_NODES];
__device__ float  g_nt[E_EDGES];            // norm with type packed in low 4 mantissa bits
__device__ float4 g_W[L_LAYERS * R_RELS];   // (w00,w01,w10,w11) per [l][r]
__device__ float  g_acc;

// ---------------------------------------------------------------------------
__global__ void compute_weights_kernel(const float* __restrict__ V,
                                       const float* __restrict__ comp) {
    int tid = threadIdx.x;
    if (tid >= L_LAYERS * R_RELS) return;
    int l = tid / R_RELS, r = tid % R_RELS;
    float w0 = 0.f, w1 = 0.f, w2 = 0.f, w3 = 0.f;
    #pragma unroll
    for (int b = 0; b < B_BASES; b++) {
        float c = comp[(l * R_RELS + r) * B_BASES + b];
        const float* v = V + ((l * B_BASES + b) * 4);
        w0 += c * v[0]; w1 += c * v[1]; w2 += c * v[2]; w3 += c * v[3];
    }
    g_W[tid] = make_float4(w0, w1, w2, w3);
}

// h = 0; acc = 0   (float4 writes, 2 nodes/thread)
__global__ void zero_kernel() {
    int i = blockIdx.x * blockDim.x + threadIdx.x;
    if (i == 0) g_acc = 0.f;
    if (i < N_NODES / 2)
        ((float4*)g_h)[i] = make_float4(0.f, 0.f, 0.f, 0.f);
}

// ---------------------------------------------------------------------------
// Layer 0 edge kernel: reads raw 4 arrays, computes, and writes the packed
// (norm|type) stream for layers 1-3 (sequential 16B per thread).
__global__ void __launch_bounds__(256) edge0_kernel(
        const float2* __restrict__ xin,
        const int4* __restrict__ src4,
        const int4* __restrict__ dst4,
        const int4* __restrict__ type4,
        const float4* __restrict__ norm4) {
    __shared__ float4 sW[R_RELS];
    if (threadIdx.x < R_RELS) sW[threadIdx.x] = g_W[threadIdx.x];
    __syncthreads();

    int i = blockIdx.x * blockDim.x + threadIdx.x;
    if (i >= E_EDGES / 4) return;

    int4   s  = __ldcs(&src4[i]);
    int4   d  = __ldcs(&dst4[i]);
    int4   t  = __ldcs(&type4[i]);
    float4 nm = __ldcs(&norm4[i]);

    int   ss[4] = {s.x, s.y, s.z, s.w};
    int   dd[4] = {d.x, d.y, d.z, d.w};
    int   tt[4] = {t.x, t.y, t.z, t.w};
    float nn[4] = {nm.x, nm.y, nm.z, nm.w};

    // pack (norm & ~0xF) | type -> nt stream for later layers
    float pk[4];
    #pragma unroll
    for (int k = 0; k < 4; k++)
        pk[k] = __int_as_float((__float_as_int(nn[k]) & ~0xF) | tt[k]);
    ((float4*)g_nt)[i] = make_float4(pk[0], pk[1], pk[2], pk[3]);

    #pragma unroll
    for (int k = 0; k < 4; k++) {
        float2 xs = __ldg(&xin[ss[k]]);
        float4 w = sW[tt[k]];
        float mx = (xs.x * w.x + xs.y * w.z) * nn[k];
        float my = (xs.x * w.y + xs.y * w.w) * nn[k];
        atomicAdd(&g_h[dd[k]], make_float2(mx, my));
    }
}

// ---------------------------------------------------------------------------
// Layers 1-3: stream src, dst, packed nt (12 B/edge). Type from nt low bits;
// norm with those bits zeroed (<=16 ulp perturbation, well under tolerance).
__global__ void __launch_bounds__(256) edge_kernel(
        const float2* __restrict__ xin,
        const int4* __restrict__ src4,
        const int4* __restrict__ dst4,
        int l) {
    __shared__ float4 sW[R_RELS];
    if (threadIdx.x < R_RELS) sW[threadIdx.x] = g_W[l * R_RELS + threadIdx.x];
    __syncthreads();

    int i = blockIdx.x * blockDim.x + threadIdx.x;
    if (i >= E_EDGES / 4) return;

    int4   s  = __ldcs(&src4[i]);
    int4   d  = __ldcs(&dst4[i]);
    float4 nt = __ldcs(&((const float4*)g_nt)[i]);

    int   ss[4] = {s.x, s.y, s.z, s.w};
    int   dd[4] = {d.x, d.y, d.z, d.w};
    int   nb[4] = {__float_as_int(nt.x), __float_as_int(nt.y),
                   __float_as_int(nt.z), __float_as_int(nt.w)};

    #pragma unroll
    for (int k = 0; k < 4; k++) {
        float2 xs = __ldg(&xin[ss[k]]);
        float4 w = sW[nb[k] & 0xF];
        float nrm = __int_as_float(nb[k] & ~0xF);
        float mx = (xs.x * w.x + xs.y * w.z) * nrm;
        float my = (xs.x * w.y + xs.y * w.w) * nrm;
        atomicAdd(&g_h[dd[k]], make_float2(mx, my));
    }
}

// ---------------------------------------------------------------------------
// Epilogues (2 nodes/thread, float4): consume h, produce x, re-zero h.
__global__ void epi_relu_kernel(int l, const float* __restrict__ bias) {
    int i = blockIdx.x * blockDim.x + threadIdx.x;
    if (i >= N_NODES / 2) return;
    float bx = __ldg(&bias[2 * l]), by = __ldg(&bias[2 * l + 1]);
    float4 h = ((const float4*)g_h)[i];
    ((float4*)g_x)[i] = make_float4(fmaxf(h.x + bx, 0.f), fmaxf(h.y + by, 0.f),
                                    fmaxf(h.z + bx, 0.f), fmaxf(h.w + by, 0.f));
    ((float4*)g_h)[i] = make_float4(0.f, 0.f, 0.f, 0.f);
}

// After layer 1: x = relu(h + b1) + feat; skip = x
__global__ void epi_skip_kernel(const float* __restrict__ bias,
                                const float4* __restrict__ feat4) {
    int i = blockIdx.x * blockDim.x + threadIdx.x;
    if (i >= N_NODES / 2) return;
    float bx = __ldg(&bias[2]), by = __ldg(&bias[3]);
    float4 h = ((const float4*)g_h)[i];
    float4 f = feat4[i];
    float4 v = make_float4(fmaxf(h.x + bx, 0.f) + f.x,
                           fmaxf(h.y + by, 0.f) + f.y,
                           fmaxf(h.z + bx, 0.f) + f.z,
                           fmaxf(h.w + by, 0.f) + f.w);
    ((float4*)g_x)[i] = v;
    ((float4*)g_skip)[i] = v;
    ((float4*)g_h)[i] = make_float4(0.f, 0.f, 0.f, 0.f);
}

// ---------------------------------------------------------------------------
// Fused final epilogue + dot:  acc += w . ((h3 + b3) + skip)
__global__ void dot_kernel(const float4* __restrict__ w4,
                           const float* __restrict__ bias) {
    float b3x = __ldg(&bias[6]);
    float b3y = __ldg(&bias[7]);
    const int npairs = N_NODES / 2;
    float sum = 0.f;
    for (int i = blockIdx.x * blockDim.x + threadIdx.x; i < npairs;
         i += gridDim.x * blockDim.x) {
        float4 w = __ldcs(&w4[i]);
        float4 h = ((const float4*)g_h)[i];
        float4 sk = ((const float4*)g_skip)[i];
        sum += w.x * (h.x + b3x + sk.x) + w.y * (h.y + b3y + sk.y)
             + w.z * (h.z + b3x + sk.z) + w.w * (h.w + b3y + sk.w);
    }
    #pragma unroll
    for (int off = 16; off > 0; off >>= 1)
        sum += __shfl_down_sync(0xFFFFFFFFu, sum, off);
    __shared__ float ws[8];
    int lane = threadIdx.x & 31, wid = threadIdx.x >> 5;
    if (lane == 0) ws[wid] = sum;
    __syncthreads();
    if (wid == 0) {
        sum = (lane < (blockDim.x >> 5)) ? ws[lane] : 0.f;
        #pragma unroll
        for (int off = 4; off > 0; off >>= 1)
            sum += __shfl_down_sync(0xFFFFFFFFu, sum, off);
        if (lane == 0) atomicAdd(&g_acc, sum);
    }
}

__global__ void finalize_kernel(const float* __restrict__ b_mlp,
                                float* __restrict__ out) {
    float logit = g_acc + b_mlp[0];
    out[0] = 1.f / (1.f + expf(-logit));
}

// ---------------------------------------------------------------------------
extern "C" void kernel_launch(void* const* d_in, const int* in_sizes, int n_in,
                              void* d_out, int out_size) {
    const float* features  = (const float*)d_in[0];
    const float* norm      = (const float*)d_in[1];
    const float* V         = (const float*)d_in[2];
    const float* comp      = (const float*)d_in[3];
    const float* bias      = (const float*)d_in[4];
    const float* w_mlp     = (const float*)d_in[5];
    const float* b_mlp     = (const float*)d_in[6];
    const int*   edge_src  = (const int*)d_in[7];
    const int*   edge_dst  = (const int*)d_in[8];
    const int*   edge_type = (const int*)d_in[9];
    float*       out       = (float*)d_out;

    const int TB = 256;
    const int half_blocks = (N_NODES / 2 + TB - 1) / TB;
    const int edge_blocks = (E_EDGES / 4 + TB - 1) / TB;   // 15625

    const int4*   s4 = (const int4*)edge_src;
    const int4*   d4 = (const int4*)edge_dst;
    const int4*   t4 = (const int4*)edge_type;
    const float4* n4 = (const float4*)norm;

    void* px = nullptr;
    cudaGetSymbolAddress(&px, g_x);
    const float2* fx = (const float2*)px;

    compute_weights_kernel<<<1, 64>>>(V, comp);
    zero_kernel<<<half_blocks, TB>>>();

    // L0: gather features directly; also emit packed nt stream
    edge0_kernel<<<edge_blocks, TB>>>((const float2*)features, s4, d4, t4, n4);
    epi_relu_kernel<<<half_blocks, TB>>>(0, bias);

    edge_kernel<<<edge_blocks, TB>>>(fx, s4, d4, 1);
    epi_skip_kernel<<<half_blocks, TB>>>(bias, (const float4*)features);

    edge_kernel<<<edge_blocks, TB>>>(fx, s4, d4, 2);
    epi_relu_kernel<<<half_blocks, TB>>>(2, bias);

    edge_kernel<<<edge_blocks, TB>>>(fx, s4, d4, 3);

    dot_kernel<<<1024, TB>>>((const float4*)w_mlp, bias);
    finalize_kernel<<<1, 1>>>(b_mlp, out);
}

// round 12
// speedup vs baseline: 1.0079x; 1.0040x over previous
#include <cuda_runtime.h>
#include <cuda_bf16.h>
#include <math.h>

#define H_DIM 2
#define L_LAYERS 4
#define R_RELS 16
#define B_BASES 8
#define N_NODES 1000000
#define E_EDGES 16000000

// ---- device scratch (allocation-free rule) --------------------------------
__device__ float2 g_x[N_NODES];
__device__ float2 g_h[N_NODES];
__device__ float2 g_skip[N_NODES];
__device__ float4 g_W[L_LAYERS * R_RELS];   // (w00,w01,w10,w11) per [l][r]
__device__ float  g_acc;

// ---------------------------------------------------------------------------
__global__ void compute_weights_kernel(const float* __restrict__ V,
                                       const float* __restrict__ comp) {
    int tid = threadIdx.x;
    if (tid >= L_LAYERS * R_RELS) return;
    int l = tid / R_RELS, r = tid % R_RELS;
    float w0 = 0.f, w1 = 0.f, w2 = 0.f, w3 = 0.f;
    #pragma unroll
    for (int b = 0; b < B_BASES; b++) {
        float c = comp[(l * R_RELS + r) * B_BASES + b];
        const float* v = V + ((l * B_BASES + b) * 4);
        w0 += c * v[0]; w1 += c * v[1]; w2 += c * v[2]; w3 += c * v[3];
    }
    g_W[tid] = make_float4(w0, w1, w2, w3);
}

// h = 0; acc = 0   (float4 writes, 2 nodes/thread)
__global__ void zero_kernel() {
    int i = blockIdx.x * blockDim.x + threadIdx.x;
    if (i == 0) g_acc = 0.f;
    if (i < N_NODES / 2)
        ((float4*)g_h)[i] = make_float4(0.f, 0.f, 0.f, 0.f);
}

// ---------------------------------------------------------------------------
// Edge kernel (measured floor): 4 edges/thread, __ldcs evict-first streams,
// L2-hit gathers, float2 RED scatter. ~2.5 LTS sectors/edge.
__global__ void __launch_bounds__(256) edge_kernel(
        const float2* __restrict__ xin,
        const int4* __restrict__ src4,
        const int4* __restrict__ dst4,
        const int4* __restrict__ type4,
        const float4* __restrict__ norm4,
        int l) {
    __shared__ float4 sW[R_RELS];
    if (threadIdx.x < R_RELS) sW[threadIdx.x] = g_W[l * R_RELS + threadIdx.x];
    __syncthreads();

    int i = blockIdx.x * blockDim.x + threadIdx.x;
    if (i >= E_EDGES / 4) return;

    int4   s  = __ldcs(&src4[i]);
    int4   d  = __ldcs(&dst4[i]);
    int4   t  = __ldcs(&type4[i]);
    float4 nm = __ldcs(&norm4[i]);

    int   ss[4] = {s.x, s.y, s.z, s.w};
    int   dd[4] = {d.x, d.y, d.z, d.w};
    int   tt[4] = {t.x, t.y, t.z, t.w};
    float nn[4] = {nm.x, nm.y, nm.z, nm.w};

    #pragma unroll
    for (int k = 0; k < 4; k++) {
        float2 xs = __ldg(&xin[ss[k]]);
        float4 w = sW[tt[k]];
        float mx = (xs.x * w.x + xs.y * w.z) * nn[k];
        float my = (xs.x * w.y + xs.y * w.w) * nn[k];
        atomicAdd(&g_h[dd[k]], make_float2(mx, my));
    }
}

// ---------------------------------------------------------------------------
// Epilogues (2 nodes/thread, float4): consume h, produce x, re-zero h.
// After layers 0 and 2:  x = relu(h + b)
__global__ void epi_relu_kernel(int l, const float* __restrict__ bias) {
    int i = blockIdx.x * blockDim.x + threadIdx.x;
    if (i >= N_NODES / 2) return;
    float bx = __ldg(&bias[2 * l]), by = __ldg(&bias[2 * l + 1]);
    float4 h = ((const float4*)g_h)[i];
    ((float4*)g_x)[i] = make_float4(fmaxf(h.x + bx, 0.f), fmaxf(h.y + by, 0.f),
                                    fmaxf(h.z + bx, 0.f), fmaxf(h.w + by, 0.f));
    ((float4*)g_h)[i] = make_float4(0.f, 0.f, 0.f, 0.f);
}

// After layer 1:  x = relu(h + b1) + features;  skip = x
__global__ void epi_skip_kernel(const float* __restrict__ bias,
                                const float4* __restrict__ feat4) {
    int i = blockIdx.x * blockDim.x + threadIdx.x;
    if (i >= N_NODES / 2) return;
    float bx = __ldg(&bias[2]), by = __ldg(&bias[3]);
    float4 h = ((const float4*)g_h)[i];
    float4 f = feat4[i];
    float4 v = make_float4(fmaxf(h.x + bx, 0.f) + f.x,
                           fmaxf(h.y + by, 0.f) + f.y,
                           fmaxf(h.z + bx, 0.f) + f.z,
                           fmaxf(h.w + by, 0.f) + f.w);
    ((float4*)g_x)[i] = v;
    ((float4*)g_skip)[i] = v;
    ((float4*)g_h)[i] = make_float4(0.f, 0.f, 0.f, 0.f);
}

// ---------------------------------------------------------------------------
// Fused final epilogue + dot:  acc += w . ((h3 + b3) + skip)
__global__ void dot_kernel(const float4* __restrict__ w4,
                           const float* __restrict__ bias) {
    float b3x = __ldg(&bias[6]);
    float b3y = __ldg(&bias[7]);
    const int npairs = N_NODES / 2;
    float sum = 0.f;
    for (int i = blockIdx.x * blockDim.x + threadIdx.x; i < npairs;
         i += gridDim.x * blockDim.x) {
        float4 w = __ldcs(&w4[i]);
        float4 h = ((const float4*)g_h)[i];
        float4 sk = ((const float4*)g_skip)[i];
        sum += w.x * (h.x + b3x + sk.x) + w.y * (h.y + b3y + sk.y)
             + w.z * (h.z + b3x + sk.z) + w.w * (h.w + b3y + sk.w);
    }
    #pragma unroll
    for (int off = 16; off > 0; off >>= 1)
        sum += __shfl_down_sync(0xFFFFFFFFu, sum, off);
    __shared__ float ws[8];
    int lane = threadIdx.x & 31, wid = threadIdx.x >> 5;
    if (lane == 0) ws[wid] = sum;
    __syncthreads();
    if (wid == 0) {
        sum = (lane < (blockDim.x >> 5)) ? ws[lane] : 0.f;
        #pragma unroll
        for (int off = 4; off > 0; off >>= 1)
            sum += __shfl_down_sync(0xFFFFFFFFu, sum, off);
        if (lane == 0) atomicAdd(&g_acc, sum);
    }
}

__global__ void finalize_kernel(const float* __restrict__ b_mlp,
                                float* __restrict__ out) {
    float logit = g_acc + b_mlp[0];
    out[0] = 1.f / (1.f + expf(-logit));
}

// ---------------------------------------------------------------------------
extern "C" void kernel_launch(void* const* d_in, const int* in_sizes, int n_in,
                              void* d_out, int out_size) {
    const float* features  = (const float*)d_in[0];
    const float* norm      = (const float*)d_in[1];
    const float* V         = (const float*)d_in[2];
    const float* comp      = (const float*)d_in[3];
    const float* bias      = (const float*)d_in[4];
    const float* w_mlp     = (const float*)d_in[5];
    const float* b_mlp     = (const float*)d_in[6];
    const int*   edge_src  = (const int*)d_in[7];
    const int*   edge_dst  = (const int*)d_in[8];
    const int*   edge_type = (const int*)d_in[9];
    float*       out       = (float*)d_out;

    const int TB = 256;
    const int half_blocks = (N_NODES / 2 + TB - 1) / TB;
    const int edge_blocks = (E_EDGES / 4 + TB - 1) / TB;   // 15625

    const int4*   s4 = (const int4*)edge_src;
    const int4*   d4 = (const int4*)edge_dst;
    const int4*   t4 = (const int4*)edge_type;
    const float4* n4 = (const float4*)norm;

    void* px = nullptr;
    cudaGetSymbolAddress(&px, g_x);
    const float2* fx = (const float2*)px;

    compute_weights_kernel<<<1, 64>>>(V, comp);
    zero_kernel<<<half_blocks, TB>>>();

    // L0: gather features directly
    edge_kernel<<<edge_blocks, TB>>>((const float2*)features, s4, d4, t4, n4, 0);
    epi_relu_kernel<<<half_blocks, TB>>>(0, bias);

    edge_kernel<<<edge_blocks, TB>>>(fx, s4, d4, t4, n4, 1);
    epi_skip_kernel<<<half_blocks, TB>>>(bias, (const float4*)features);

    edge_kernel<<<edge_blocks, TB>>>(fx, s4, d4, t4, n4, 2);
    epi_relu_kernel<<<half_blocks, TB>>>(2, bias);

    edge_kernel<<<edge_blocks, TB>>>(fx, s4, d4, t4, n4, 3);

    dot_kernel<<<1024, TB>>>((const float4*)w_mlp, bias);
    finalize_kernel<<<1, 1>>>(b_mlp, out);
}

// round 13
// speedup vs baseline: 1.0141x; 1.0061x over previous
#include <cuda_runtime.h>
#include <cuda_bf16.h>
#include <math.h>

#define H_DIM 2
#define L_LAYERS 4
#define R_RELS 16
#define B_BASES 8
#define N_NODES 1000000
#define E_EDGES 16000000

// ---- device scratch (allocation-free rule) --------------------------------
__device__ float2 g_x[N_NODES];
__device__ float2 g_h[N_NODES];
__device__ float2 g_skip[N_NODES];
__device__ float4 g_W[L_LAYERS * R_RELS];   // (w00,w01,w10,w11) per [l][r]
__device__ float  g_acc;

// ---------------------------------------------------------------------------
// Fused init: W from (V, comp) in the first 64 threads of block 0; h=0, acc=0
// everywhere (grid-stride, float4).
__global__ void init_kernel(const float* __restrict__ V,
                            const float* __restrict__ comp) {
    if (blockIdx.x == 0 && threadIdx.x < L_LAYERS * R_RELS) {
        int tid = threadIdx.x;
        int l = tid / R_RELS, r = tid % R_RELS;
        float w0 = 0.f, w1 = 0.f, w2 = 0.f, w3 = 0.f;
        #pragma unroll
        for (int b = 0; b < B_BASES; b++) {
            float c = comp[(l * R_RELS + r) * B_BASES + b];
            const float* v = V + ((l * B_BASES + b) * 4);
            w0 += c * v[0]; w1 += c * v[1]; w2 += c * v[2]; w3 += c * v[3];
        }
        g_W[tid] = make_float4(w0, w1, w2, w3);
        if (tid == 0) g_acc = 0.f;
    }
    const float4 z = make_float4(0.f, 0.f, 0.f, 0.f);
    for (int i = blockIdx.x * blockDim.x + threadIdx.x; i < N_NODES / 2;
         i += gridDim.x * blockDim.x)
        ((float4*)g_h)[i] = z;
}

// ---------------------------------------------------------------------------
// Edge kernel (measured floor): 4 edges/thread, __ldcs evict-first streams,
// L2-hit gathers, float2 RED scatter. ~2.5 LTS sectors/edge.
__global__ void __launch_bounds__(256) edge_kernel(
        const float2* __restrict__ xin,
        const int4* __restrict__ src4,
        const int4* __restrict__ dst4,
        const int4* __restrict__ type4,
        const float4* __restrict__ norm4,
        int l) {
    __shared__ float4 sW[R_RELS];
    if (threadIdx.x < R_RELS) sW[threadIdx.x] = g_W[l * R_RELS + threadIdx.x];
    __syncthreads();

    int i = blockIdx.x * blockDim.x + threadIdx.x;
    if (i >= E_EDGES / 4) return;

    int4   s  = __ldcs(&src4[i]);
    int4   d  = __ldcs(&dst4[i]);
    int4   t  = __ldcs(&type4[i]);
    float4 nm = __ldcs(&norm4[i]);

    int   ss[4] = {s.x, s.y, s.z, s.w};
    int   dd[4] = {d.x, d.y, d.z, d.w};
    int   tt[4] = {t.x, t.y, t.z, t.w};
    float nn[4] = {nm.x, nm.y, nm.z, nm.w};

    #pragma unroll
    for (int k = 0; k < 4; k++) {
        float2 xs = __ldg(&xin[ss[k]]);
        float4 w = sW[tt[k]];
        float mx = (xs.x * w.x + xs.y * w.z) * nn[k];
        float my = (xs.x * w.y + xs.y * w.w) * nn[k];
        atomicAdd(&g_h[dd[k]], make_float2(mx, my));
    }
}

// ---------------------------------------------------------------------------
// Epilogues (2 nodes/thread, float4): consume h, produce x, re-zero h.
// After layers 0 and 2:  x = relu(h + b)
__global__ void epi_relu_kernel(int l, const float* __restrict__ bias) {
    int i = blockIdx.x * blockDim.x + threadIdx.x;
    if (i >= N_NODES / 2) return;
    float bx = __ldg(&bias[2 * l]), by = __ldg(&bias[2 * l + 1]);
    float4 h = ((const float4*)g_h)[i];
    ((float4*)g_x)[i] = make_float4(fmaxf(h.x + bx, 0.f), fmaxf(h.y + by, 0.f),
                                    fmaxf(h.z + bx, 0.f), fmaxf(h.w + by, 0.f));
    ((float4*)g_h)[i] = make_float4(0.f, 0.f, 0.f, 0.f);
}

// After layer 1:  x = relu(h + b1) + features;  skip = x
__global__ void epi_skip_kernel(const float* __restrict__ bias,
                                const float4* __restrict__ feat4) {
    int i = blockIdx.x * blockDim.x + threadIdx.x;
    if (i >= N_NODES / 2) return;
    float bx = __ldg(&bias[2]), by = __ldg(&bias[3]);
    float4 h = ((const float4*)g_h)[i];
    float4 f = __ldcs(&feat4[i]);
    float4 v = make_float4(fmaxf(h.x + bx, 0.f) + f.x,
                           fmaxf(h.y + by, 0.f) + f.y,
                           fmaxf(h.z + bx, 0.f) + f.z,
                           fmaxf(h.w + by, 0.f) + f.w);
    ((float4*)g_x)[i] = v;
    ((float4*)g_skip)[i] = v;
    ((float4*)g_h)[i] = make_float4(0.f, 0.f, 0.f, 0.f);
}

// ---------------------------------------------------------------------------
// Fused final epilogue + dot:  acc += w . ((h3 + b3) + skip)
__global__ void dot_kernel(const float4* __restrict__ w4,
                           const float* __restrict__ bias) {
    float b3x = __ldg(&bias[6]);
    float b3y = __ldg(&bias[7]);
    const int npairs = N_NODES / 2;
    float sum = 0.f;
    for (int i = blockIdx.x * blockDim.x + threadIdx.x; i < npairs;
         i += gridDim.x * blockDim.x) {
        float4 w  = __ldcs(&w4[i]);
        float4 h  = __ldcs(&((const float4*)g_h)[i]);
        float4 sk = __ldcs(&((const float4*)g_skip)[i]);
        sum += w.x * (h.x + b3x + sk.x) + w.y * (h.y + b3y + sk.y)
             + w.z * (h.z + b3x + sk.z) + w.w * (h.w + b3y + sk.w);
    }
    #pragma unroll
    for (int off = 16; off > 0; off >>= 1)
        sum += __shfl_down_sync(0xFFFFFFFFu, sum, off);
    __shared__ float ws[8];
    int lane = threadIdx.x & 31, wid = threadIdx.x >> 5;
    if (lane == 0) ws[wid] = sum;
    __syncthreads();
    if (wid == 0) {
        sum = (lane < (blockDim.x >> 5)) ? ws[lane] : 0.f;
        #pragma unroll
        for (int off = 4; off > 0; off >>= 1)
            sum += __shfl_down_sync(0xFFFFFFFFu, sum, off);
        if (lane == 0) atomicAdd(&g_acc, sum);
    }
}

__global__ void finalize_kernel(const float* __restrict__ b_mlp,
                                float* __restrict__ out) {
    float logit = g_acc + b_mlp[0];
    out[0] = 1.f / (1.f + expf(-logit));
}

// ---------------------------------------------------------------------------
extern "C" void kernel_launch(void* const* d_in, const int* in_sizes, int n_in,
                              void* d_out, int out_size) {
    const float* features  = (const float*)d_in[0];
    const float* norm      = (const float*)d_in[1];
    const float* V         = (const float*)d_in[2];
    const float* comp      = (const float*)d_in[3];
    const float* bias      = (const float*)d_in[4];
    const float* w_mlp     = (const float*)d_in[5];
    const float* b_mlp     = (const float*)d_in[6];
    const int*   edge_src  = (const int*)d_in[7];
    const int*   edge_dst  = (const int*)d_in[8];
    const int*   edge_type = (const int*)d_in[9];
    float*       out       = (float*)d_out;

    const int TB = 256;
    const int half_blocks = (N_NODES / 2 + TB - 1) / TB;
    const int edge_blocks = (E_EDGES / 4 + TB - 1) / TB;   // 15625

    const int4*   s4 = (const int4*)edge_src;
    const int4*   d4 = (const int4*)edge_dst;
    const int4*   t4 = (const int4*)edge_type;
    const float4* n4 = (const float4*)norm;

    void* px = nullptr;
    cudaGetSymbolAddress(&px, g_x);
    const float2* fx = (const float2*)px;

    init_kernel<<<148 * 8, TB>>>(V, comp);

    // L0: gather features directly
    edge_kernel<<<edge_blocks, TB>>>((const float2*)features, s4, d4, t4, n4, 0);
    epi_relu_kernel<<<half_blocks, TB>>>(0, bias);

    edge_kernel<<<edge_blocks, TB>>>(fx, s4, d4, t4, n4, 1);
    epi_skip_kernel<<<half_blocks, TB>>>(bias, (const float4*)features);

    edge_kernel<<<edge_blocks, TB>>>(fx, s4, d4, t4, n4, 2);
    epi_relu_kernel<<<half_blocks, TB>>>(2, bias);

    edge_kernel<<<edge_blocks, TB>>>(fx, s4, d4, t4, n4, 3);

    dot_kernel<<<1024, TB>>>((const float4*)w_mlp, bias);
    finalize_kernel<<<1, 1>>>(b_mlp, out);
}

// round 14
// speedup vs baseline: 1.0146x; 1.0005x over previous
#include <cuda_runtime.h>
#include <cuda_bf16.h>
#include <math.h>

#define H_DIM 2
#define L_LAYERS 4
#define R_RELS 16
#define B_BASES 8
#define N_NODES 1000000
#define E_EDGES 16000000

// ---- device scratch (allocation-free rule) --------------------------------
__device__ float2 g_x[N_NODES];
__device__ float2 g_h[N_NODES];
__device__ float2 g_skip[N_NODES];
__device__ float4 g_W[L_LAYERS * R_RELS];   // (w00,w01,w10,w11) per [l][r]
__device__ float  g_acc;

// ---------------------------------------------------------------------------
// Fused init: W from (V, comp) in the first 64 threads of block 0; h=0, acc=0
// everywhere (grid-stride, float4).
__global__ void init_kernel(const float* __restrict__ V,
                            const float* __restrict__ comp) {
    if (blockIdx.x == 0 && threadIdx.x < L_LAYERS * R_RELS) {
        int tid = threadIdx.x;
        int l = tid / R_RELS, r = tid % R_RELS;
        float w0 = 0.f, w1 = 0.f, w2 = 0.f, w3 = 0.f;
        #pragma unroll
        for (int b = 0; b < B_BASES; b++) {
            float c = comp[(l * R_RELS + r) * B_BASES + b];
            const float* v = V + ((l * B_BASES + b) * 4);
            w0 += c * v[0]; w1 += c * v[1]; w2 += c * v[2]; w3 += c * v[3];
        }
        g_W[tid] = make_float4(w0, w1, w2, w3);
        if (tid == 0) g_acc = 0.f;
    }
    const float4 z = make_float4(0.f, 0.f, 0.f, 0.f);
    for (int i = blockIdx.x * blockDim.x + threadIdx.x; i < N_NODES / 2;
         i += gridDim.x * blockDim.x)
        ((float4*)g_h)[i] = z;
}

// ---------------------------------------------------------------------------
// Edge kernel (measured floor): 4 edges/thread, __ldcs evict-first streams,
// L2-hit gathers, float2 RED scatter. ~2.5 LTS sectors/edge.
__global__ void __launch_bounds__(256) edge_kernel(
        const float2* __restrict__ xin,
        const int4* __restrict__ src4,
        const int4* __restrict__ dst4,
        const int4* __restrict__ type4,
        const float4* __restrict__ norm4,
        int l) {
    __shared__ float4 sW[R_RELS];
    if (threadIdx.x < R_RELS) sW[threadIdx.x] = g_W[l * R_RELS + threadIdx.x];
    __syncthreads();

    int i = blockIdx.x * blockDim.x + threadIdx.x;
    if (i >= E_EDGES / 4) return;

    int4   s  = __ldcs(&src4[i]);
    int4   d  = __ldcs(&dst4[i]);
    int4   t  = __ldcs(&type4[i]);
    float4 nm = __ldcs(&norm4[i]);

    int   ss[4] = {s.x, s.y, s.z, s.w};
    int   dd[4] = {d.x, d.y, d.z, d.w};
    int   tt[4] = {t.x, t.y, t.z, t.w};
    float nn[4] = {nm.x, nm.y, nm.z, nm.w};

    #pragma unroll
    for (int k = 0; k < 4; k++) {
        float2 xs = __ldg(&xin[ss[k]]);
        float4 w = sW[tt[k]];
        float mx = (xs.x * w.x + xs.y * w.z) * nn[k];
        float my = (xs.x * w.y + xs.y * w.w) * nn[k];
        atomicAdd(&g_h[dd[k]], make_float2(mx, my));
    }
}

// ---------------------------------------------------------------------------
// Epilogues (2 nodes/thread, float4): consume h, produce x, re-zero h.
// h is read-once (then overwritten) -> __ldcs keeps L1 clean for gathers.
// After layers 0 and 2:  x = relu(h + b)
__global__ void epi_relu_kernel(int l, const float* __restrict__ bias) {
    int i = blockIdx.x * blockDim.x + threadIdx.x;
    if (i >= N_NODES / 2) return;
    float bx = __ldg(&bias[2 * l]), by = __ldg(&bias[2 * l + 1]);
    float4 h = __ldcs(&((const float4*)g_h)[i]);
    ((float4*)g_x)[i] = make_float4(fmaxf(h.x + bx, 0.f), fmaxf(h.y + by, 0.f),
                                    fmaxf(h.z + bx, 0.f), fmaxf(h.w + by, 0.f));
    ((float4*)g_h)[i] = make_float4(0.f, 0.f, 0.f, 0.f);
}

// After layer 1:  x = relu(h + b1) + features;  skip = x
__global__ void epi_skip_kernel(const float* __restrict__ bias,
                                const float4* __restrict__ feat4) {
    int i = blockIdx.x * blockDim.x + threadIdx.x;
    if (i >= N_NODES / 2) return;
    float bx = __ldg(&bias[2]), by = __ldg(&bias[3]);
    float4 h = __ldcs(&((const float4*)g_h)[i]);
    float4 f = __ldcs(&feat4[i]);
    float4 v = make_float4(fmaxf(h.x + bx, 0.f) + f.x,
                           fmaxf(h.y + by, 0.f) + f.y,
                           fmaxf(h.z + bx, 0.f) + f.z,
                           fmaxf(h.w + by, 0.f) + f.w);
    ((float4*)g_x)[i] = v;
    ((float4*)g_skip)[i] = v;
    ((float4*)g_h)[i] = make_float4(0.f, 0.f, 0.f, 0.f);
}

// ---------------------------------------------------------------------------
// Fused final epilogue + dot:  acc += w . ((h3 + b3) + skip)
__global__ void dot_kernel(const float4* __restrict__ w4,
                           const float* __restrict__ bias) {
    float b3x = __ldg(&bias[6]);
    float b3y = __ldg(&bias[7]);
    const int npairs = N_NODES / 2;
    float sum = 0.f;
    for (int i = blockIdx.x * blockDim.x + threadIdx.x; i < npairs;
         i += gridDim.x * blockDim.x) {
        float4 w  = __ldcs(&w4[i]);
        float4 h  = __ldcs(&((const float4*)g_h)[i]);
        float4 sk = __ldcs(&((const float4*)g_skip)[i]);
        sum += w.x * (h.x + b3x + sk.x) + w.y * (h.y + b3y + sk.y)
             + w.z * (h.z + b3x + sk.z) + w.w * (h.w + b3y + sk.w);
    }
    #pragma unroll
    for (int off = 16; off > 0; off >>= 1)
        sum += __shfl_down_sync(0xFFFFFFFFu, sum, off);
    __shared__ float ws[8];
    int lane = threadIdx.x & 31, wid = threadIdx.x >> 5;
    if (lane == 0) ws[wid] = sum;
    __syncthreads();
    if (wid == 0) {
        sum = (lane < (blockDim.x >> 5)) ? ws[lane] : 0.f;
        #pragma unroll
        for (int off = 4; off > 0; off >>= 1)
            sum += __shfl_down_sync(0xFFFFFFFFu, sum, off);
        if (lane == 0) atomicAdd(&g_acc, sum);
    }
}

__global__ void finalize_kernel(const float* __restrict__ b_mlp,
                                float* __restrict__ out) {
    float logit = g_acc + b_mlp[0];
    out[0] = 1.f / (1.f + expf(-logit));
}

// ---------------------------------------------------------------------------
extern "C" void kernel_launch(void* const* d_in, const int* in_sizes, int n_in,
                              void* d_out, int out_size) {
    const float* features  = (const float*)d_in[0];
    const float* norm      = (const float*)d_in[1];
    const float* V         = (const float*)d_in[2];
    const float* comp      = (const float*)d_in[3];
    const float* bias      = (const float*)d_in[4];
    const float* w_mlp     = (const float*)d_in[5];
    const float* b_mlp     = (const float*)d_in[6];
    const int*   edge_src  = (const int*)d_in[7];
    const int*   edge_dst  = (const int*)d_in[8];
    const int*   edge_type = (const int*)d_in[9];
    float*       out       = (float*)d_out;

    const int TB = 256;
    const int half_blocks = (N_NODES / 2 + TB - 1) / TB;
    const int edge_blocks = (E_EDGES / 4 + TB - 1) / TB;   // 15625

    const int4*   s4 = (const int4*)edge_src;
    const int4*   d4 = (const int4*)edge_dst;
    const int4*   t4 = (const int4*)edge_type;
    const float4* n4 = (const float4*)norm;

    void* px = nullptr;
    cudaGetSymbolAddress(&px, g_x);
    const float2* fx = (const float2*)px;

    init_kernel<<<148 * 8, TB>>>(V, comp);

    // L0: gather features directly
    edge_kernel<<<edge_blocks, TB>>>((const float2*)features, s4, d4, t4, n4, 0);
    epi_relu_kernel<<<half_blocks, TB>>>(0, bias);

    edge_kernel<<<edge_blocks, TB>>>(fx, s4, d4, t4, n4, 1);
    epi_skip_kernel<<<half_blocks, TB>>>(bias, (const float4*)features);

    edge_kernel<<<edge_blocks, TB>>>(fx, s4, d4, t4, n4, 2);
    epi_relu_kernel<<<half_blocks, TB>>>(2, bias);

    edge_kernel<<<edge_blocks, TB>>>(fx, s4, d4, t4, n4, 3);

    dot_kernel<<<2048, TB>>>((const float4*)w_mlp, bias);
    finalize_kernel<<<1, 1>>>(b_mlp, out);
}